// round 10
// baseline (speedup 1.0000x reference)
#include <cuda_runtime.h>
#include <cuda_bf16.h>
#include <cstdint>

constexpr int STATE = 2048;
constexpr int SEQL  = 4096;
constexpr int HID   = 1024;
constexpr int KP    = 3 * HID;     // [hi|hi|lo] x [hi|lo|hi] split-K layout

constexpr int BM  = 128;
constexpr int BK  = 64;            // 64 bf16 = 128B row = one SW128 atom
constexpr int NIT = KP / BK;       // 48
constexpr int NTHR = 256;
constexpr int NSTG = 3;

__device__ __align__(128) __nv_bfloat16 g_idS  [(size_t)SEQL  * KP];  // pat1
__device__ __align__(128) __nv_bfloat16 g_WTS  [(size_t)HID   * KP];  // W^T, pat1
__device__ __align__(128) __nv_bfloat16 g_combS[(size_t)STATE * KP];  // pat0
__device__ __align__(128) __nv_bfloat16 g_PS   [(size_t)STATE * KP];  // P=comb@W, pat0

// ---------------------------------------------------------------------------
__device__ __forceinline__ uint32_t smem_u32(const void* p) {
    uint32_t a;
    asm("{ .reg .u64 t; cvta.to.shared.u64 t, %1; cvt.u32.u64 %0, t; }" : "=r"(a) : "l"(p));
    return a;
}
__device__ __forceinline__ uint32_t sw128(uint32_t off) { return off ^ ((off >> 3) & 0x70); }
__device__ __forceinline__ void cp_async16(uint32_t s, const void* g) {
    asm volatile("cp.async.cg.shared.global [%0], [%1], 16;" :: "r"(s), "l"(g) : "memory");
}
__device__ __forceinline__ void ldsm_x4(uint32_t* r, uint32_t addr) {
    asm volatile("ldmatrix.sync.aligned.m8n8.x4.shared.b16 {%0,%1,%2,%3}, [%4];"
                 : "=r"(r[0]), "=r"(r[1]), "=r"(r[2]), "=r"(r[3]) : "r"(addr));
}
__device__ __forceinline__ void mma_bf16(float* c, const uint32_t* a, const uint32_t* b) {
    asm volatile(
        "mma.sync.aligned.m16n8k16.row.col.f32.bf16.bf16.f32 "
        "{%0,%1,%2,%3}, {%4,%5,%6,%7}, {%8,%9}, {%0,%1,%2,%3};"
        : "+f"(c[0]), "+f"(c[1]), "+f"(c[2]), "+f"(c[3])
        : "r"(a[0]), "r"(a[1]), "r"(a[2]), "r"(a[3]), "r"(b[0]), "r"(b[1]));
}
__device__ __forceinline__ uint32_t pack_bf16(float x, float y) {
    __nv_bfloat162 t = __floats2bfloat162_rn(x, y);
    return *reinterpret_cast<uint32_t*>(&t);
}

// ------------------ split helpers: fp32 -> bf16 (hi,lo) triplets ------------
__device__ __forceinline__ void split_store(float x0, float x1, float x2, float x3,
                                            __nv_bfloat16* dst, size_t base, int pat) {
    alignas(8) __nv_bfloat16 h[4], l[4];
    float x[4] = {x0, x1, x2, x3};
    #pragma unroll
    for (int c = 0; c < 4; c++) {
        h[c] = __float2bfloat16_rn(x[c]);
        l[c] = __float2bfloat16_rn(x[c] - __bfloat162float(h[c]));
    }
    const uint2 hw = *reinterpret_cast<uint2*>(h);
    const uint2 lw = *reinterpret_cast<uint2*>(l);
    *reinterpret_cast<uint2*>(dst + base) = hw;
    if (pat == 0) {  // A-operand: [hi|hi|lo]
        *reinterpret_cast<uint2*>(dst + base + HID)     = hw;
        *reinterpret_cast<uint2*>(dst + base + 2 * HID) = lw;
    } else {         // B-operand: [hi|lo|hi]
        *reinterpret_cast<uint2*>(dst + base + HID)     = lw;
        *reinterpret_cast<uint2*>(dst + base + 2 * HID) = hw;
    }
}

template <int PAT>
__global__ __launch_bounds__(256)
void split_kernel(const float* __restrict__ src, __nv_bfloat16* __restrict__ dst) {
    const int i = blockIdx.x * 256 + threadIdx.x;
    const float4 v = reinterpret_cast<const float4*>(src)[i];
    const int row = i >> 8;
    const int col = (i & 255) << 2;
    split_store(v.x, v.y, v.z, v.w, dst, (size_t)row * KP + col, PAT);
}

__global__ __launch_bounds__(256)
void combine_split_kernel(const float* __restrict__ u, const float* __restrict__ s,
                          const float* __restrict__ w1p, const float* __restrict__ w2p,
                          __nv_bfloat16* __restrict__ dst) {
    const float w1 = *w1p, w2 = *w2p;
    const int i = blockIdx.x * 256 + threadIdx.x;
    const float4 uv = reinterpret_cast<const float4*>(u)[i];
    const float4 sv = reinterpret_cast<const float4*>(s)[i];
    const int row = i >> 8;
    const int col = (i & 255) << 2;
    split_store(fmaf(w1, uv.x, w2 * sv.x), fmaf(w1, uv.y, w2 * sv.y),
                fmaf(w1, uv.z, w2 * sv.z), fmaf(w1, uv.w, w2 * sv.w),
                dst, (size_t)row * KP + col, 0);
}

// Transpose + split: dst[h, triplet over n] = W[n, h], pat1. 32x32 tiles.
__global__ __launch_bounds__(256)
void transpose_split_kernel(const float* __restrict__ W, __nv_bfloat16* __restrict__ dst) {
    __shared__ float ts[32][33];
    const int tx = threadIdx.x & 31;
    const int ty = threadIdx.x >> 5;
    const int n0 = blockIdx.y * 32;
    const int h0 = blockIdx.x * 32;
    #pragma unroll
    for (int j = 0; j < 4; j++)
        ts[ty + j * 8][tx] = W[(size_t)(n0 + ty + j * 8) * HID + h0 + tx];
    __syncthreads();
    const int r  = threadIdx.x >> 3;
    const int c4 = (threadIdx.x & 7) * 4;
    split_store(ts[c4 + 0][r], ts[c4 + 1][r], ts[c4 + 2][r], ts[c4 + 3][r],
                dst, (size_t)(h0 + r) * KP + n0 + c4, 1);
}

// ------------------ HMMA NT GEMM -------------------------------------------
// BM=128 fixed. TBN: tile N. WARPS_M x (8/WARPS_M) warp grid; warp cols = TBN/(8/WARPS_M)=32.
// MODE 0: fp32 out (stride Nout). MODE 1: bf16 pat0 split of D -> PS.
template <int MODE, int TBN, int WARPS_M>
__global__ __launch_bounds__(NTHR, 2)
void gemm_mma_kernel(const __nv_bfloat16* __restrict__ A,
                     const __nv_bfloat16* __restrict__ B,
                     void* __restrict__ outp, int Nout) {
    constexpr int WARPS_N = 8 / WARPS_M;
    constexpr int WROWS   = BM / WARPS_M;       // 64 or 32
    constexpr int MT      = WROWS / 16;         // 4 or 2
    constexpr int A_STG   = BM * 128;           // 16KB
    constexpr int B_STG   = TBN * 128;
    constexpr int STG     = A_STG + B_STG;
    static_assert(TBN / WARPS_N == 32, "warp tile N must be 32");

    extern __shared__ __align__(1024) char smem_raw[];
    const uint32_t sb = smem_u32(smem_raw);
    const int tid  = threadIdx.x;
    const int lane = tid & 31;
    const int wid  = tid >> 5;
    const int wm   = wid % WARPS_M;
    const int wn   = wid / WARPS_M;
    const int m0   = blockIdx.y * BM;
    const int n0   = blockIdx.x * TBN;

    auto load_stage = [&](int it) {
        const int st = (it % NSTG);
        const size_t k0 = (size_t)it * BK;
        const uint32_t sa  = sb + st * STG;
        const uint32_t sbb = sa + A_STG;
        #pragma unroll
        for (int j = 0; j < 4; j++) {              // A: 128 rows x 128B
            const int c = tid + j * NTHR;
            const int r = c >> 3, p = c & 7;
            cp_async16(sa + sw128((uint32_t)(r * 128 + p * 16)),
                       A + (size_t)(m0 + r) * KP + k0 + p * 8);
        }
        #pragma unroll
        for (int j = 0; j < TBN / 32; j++) {       // B: TBN rows x 128B
            const int c = tid + j * NTHR;
            const int r = c >> 3, p = c & 7;
            cp_async16(sbb + sw128((uint32_t)(r * 128 + p * 16)),
                       B + (size_t)(n0 + r) * KP + k0 + p * 8);
        }
        asm volatile("cp.async.commit_group;" ::: "memory");
    };

    float acc[MT][4][4];
    #pragma unroll
    for (int mt = 0; mt < MT; mt++)
        #pragma unroll
        for (int nt = 0; nt < 4; nt++)
            #pragma unroll
            for (int q = 0; q < 4; q++) acc[mt][nt][q] = 0.f;

    const uint32_t rA0 = (uint32_t)((wm * WROWS + (lane & 15)) * 128 + ((lane >> 4) << 4));
    const uint32_t rB0 = (uint32_t)((wn * 32 + ((lane >> 4) << 3) + (lane & 7)) * 128
                                    + ((lane & 8) << 1));

    load_stage(0); load_stage(1);

    for (int it = 0; it < NIT; ++it) {
        if (it + 2 < NIT) { asm volatile("cp.async.wait_group 1;" ::: "memory"); }
        else              { asm volatile("cp.async.wait_group 0;" ::: "memory"); }
        __syncthreads();
        if (it + 2 < NIT) load_stage(it + 2);

        const uint32_t sa  = sb + (it % NSTG) * STG;
        const uint32_t sbb = sa + A_STG;
        #pragma unroll
        for (int kk = 0; kk < 4; kk++) {            // 4 x k16 per BK=64
            uint32_t a[MT][4], b[2][4];
            #pragma unroll
            for (int mt2 = 0; mt2 < MT; mt2++)
                ldsm_x4(a[mt2], sa + sw128(rA0 + mt2 * 2048 + kk * 32));
            #pragma unroll
            for (int nt2 = 0; nt2 < 2; nt2++)
                ldsm_x4(b[nt2], sbb + sw128(rB0 + nt2 * 2048 + kk * 32));
            #pragma unroll
            for (int nt = 0; nt < 4; nt++) {
                const uint32_t* bp = &b[nt >> 1][(nt & 1) * 2];
                #pragma unroll
                for (int mt = 0; mt < MT; mt++)
                    mma_bf16(acc[mt][nt], a[mt], bp);
            }
        }
    }

    // ------------- epilogue (register-direct) -------------
    #pragma unroll
    for (int mt = 0; mt < MT; mt++) {
        const int r0 = m0 + wm * WROWS + mt * 16 + (lane >> 2);
        #pragma unroll
        for (int nt = 0; nt < 4; nt++) {
            const int col = n0 + wn * 32 + nt * 8 + (lane & 3) * 2;
            const float x0 = acc[mt][nt][0], x1 = acc[mt][nt][1];
            const float x2 = acc[mt][nt][2], x3 = acc[mt][nt][3];
            if (MODE == 0) {
                float* of = (float*)outp;
                *reinterpret_cast<float2*>(&of[(size_t)r0 * Nout + col])       = make_float2(x0, x1);
                *reinterpret_cast<float2*>(&of[(size_t)(r0 + 8) * Nout + col]) = make_float2(x2, x3);
            } else {
                __nv_bfloat16* ob = (__nv_bfloat16*)outp;
                {   // row r0, pat0: [hi|hi|lo]
                    const __nv_bfloat16 h0 = __float2bfloat16_rn(x0);
                    const __nv_bfloat16 h1 = __float2bfloat16_rn(x1);
                    const uint32_t hw = pack_bf16(__bfloat162float(h0), __bfloat162float(h1));
                    const uint32_t lw = pack_bf16(x0 - __bfloat162float(h0), x1 - __bfloat162float(h1));
                    const size_t base = (size_t)r0 * KP + col;
                    *reinterpret_cast<uint32_t*>(ob + base)           = hw;
                    *reinterpret_cast<uint32_t*>(ob + base + HID)     = hw;
                    *reinterpret_cast<uint32_t*>(ob + base + 2 * HID) = lw;
                }
                {   // row r0+8
                    const __nv_bfloat16 h0 = __float2bfloat16_rn(x2);
                    const __nv_bfloat16 h1 = __float2bfloat16_rn(x3);
                    const uint32_t hw = pack_bf16(__bfloat162float(h0), __bfloat162float(h1));
                    const uint32_t lw = pack_bf16(x2 - __bfloat162float(h0), x3 - __bfloat162float(h1));
                    const size_t base = (size_t)(r0 + 8) * KP + col;
                    *reinterpret_cast<uint32_t*>(ob + base)           = hw;
                    *reinterpret_cast<uint32_t*>(ob + base + HID)     = hw;
                    *reinterpret_cast<uint32_t*>(ob + base + 2 * HID) = lw;
                }
            }
        }
    }
}

// ------------------ softmax ------------------------------------------------
__global__ __launch_bounds__(256)
void softmax_kernel(float* __restrict__ data) {
    constexpr int N = SEQL;
    __shared__ float sh[N];
    __shared__ float red[256];
    const int tid = threadIdx.x;
    float* row = data + (size_t)blockIdx.x * N;

    float mx = -3.402823466e38f;
    #pragma unroll
    for (int it = 0; it < 4; ++it) {
        const int i = tid + it * 256;
        const float4 v = reinterpret_cast<const float4*>(row)[i];
        reinterpret_cast<float4*>(sh)[i] = v;
        mx = fmaxf(mx, fmaxf(fmaxf(v.x, v.y), fmaxf(v.z, v.w)));
    }
    red[tid] = mx;
    __syncthreads();
    for (int s = 128; s > 0; s >>= 1) {
        if (tid < s) red[tid] = fmaxf(red[tid], red[tid + s]);
        __syncthreads();
    }
    mx = red[0];
    __syncthreads();

    float sum = 0.f;
    #pragma unroll
    for (int it = 0; it < 4; ++it) {
        const int i = tid + it * 256;
        float4 v = reinterpret_cast<float4*>(sh)[i];
        v.x = expf(v.x - mx); v.y = expf(v.y - mx);
        v.z = expf(v.z - mx); v.w = expf(v.w - mx);
        reinterpret_cast<float4*>(sh)[i] = v;
        sum += v.x + v.y + v.z + v.w;
    }
    red[tid] = sum;
    __syncthreads();
    for (int s = 128; s > 0; s >>= 1) {
        if (tid < s) red[tid] += red[tid + s];
        __syncthreads();
    }
    const float inv = 1.f / red[0];

    #pragma unroll
    for (int it = 0; it < 4; ++it) {
        const int i = tid + it * 256;
        float4 v = reinterpret_cast<float4*>(sh)[i];
        v.x *= inv; v.y *= inv; v.z *= inv; v.w *= inv;
        reinterpret_cast<float4*>(row)[i] = v;
    }
}

// ------------------ kernel_launch ------------------------------------------
extern "C" void kernel_launch(void* const* d_in, const int* in_sizes, int n_in,
                              void* d_out, int out_size) {
    const float* user = (const float*)d_in[0];
    const float* id   = (const float*)d_in[1];
    const float* soc  = (const float*)d_in[2];
    const float* W    = (const float*)d_in[3];
    // d_in[4] = bias: unused — softmax is invariant to the per-row constant comb.b
    const float* w1   = (const float*)d_in[5];
    const float* w2   = (const float*)d_in[6];
    float* out = (float*)d_out;

    void *pIdS, *pWTS, *pCombS, *pPS;
    cudaGetSymbolAddress(&pIdS,   g_idS);
    cudaGetSymbolAddress(&pWTS,   g_WTS);
    cudaGetSymbolAddress(&pCombS, g_combS);
    cudaGetSymbolAddress(&pPS,    g_PS);
    __nv_bfloat16* idS   = (__nv_bfloat16*)pIdS;
    __nv_bfloat16* WTS   = (__nv_bfloat16*)pWTS;
    __nv_bfloat16* combS = (__nv_bfloat16*)pCombS;
    __nv_bfloat16* PS    = (__nv_bfloat16*)pPS;

    // gemm<0>: tile 128x128, warps 2Mx4N (proven 345 TF/s config)
    constexpr int SMEM0 = NSTG * (128 * 128 + 128 * 128);   // 96KB
    // gemm<1>: tile 128x64, warps 4Mx2N -> grid 256, 2 CTAs/SM
    constexpr int SMEM1 = NSTG * (128 * 128 + 64 * 128);    // 72KB
    cudaFuncSetAttribute((const void*)gemm_mma_kernel<0, 128, 2>,
                         cudaFuncAttributeMaxDynamicSharedMemorySize, SMEM0);
    cudaFuncSetAttribute((const void*)gemm_mma_kernel<1, 64, 4>,
                         cudaFuncAttributeMaxDynamicSharedMemorySize, SMEM1);

    // 1) operand splits
    combine_split_kernel<<<(STATE * HID / 4) / 256, 256>>>(user, soc, w1, w2, combS);  // pat0
    split_kernel<1><<<(SEQL * HID / 4) / 256, 256>>>(id, idS);                          // pat1
    transpose_split_kernel<<<dim3(HID / 32, HID / 32), 256>>>(W, WTS);                  // pat1

    // 2) P = comb @ W  -> pat0 split into PS      (grid 16 x 16 = 256 CTAs, 2/SM)
    gemm_mma_kernel<1, 64, 4><<<dim3(HID / 64, STATE / BM), NTHR, SMEM1>>>(combS, WTS, PS, 0);

    // 3) energies = P @ id^T -> d_out (fp32)      (grid 32 x 16 = 512 CTAs, 2/SM)
    gemm_mma_kernel<0, 128, 2><<<dim3(SEQL / 128, STATE / BM), NTHR, SMEM0>>>(PS, idS, out, SEQL);

    // 4) softmax rows in place
    softmax_kernel<<<STATE, 256>>>(out);
}

// round 12
// speedup vs baseline: 1.0270x; 1.0270x over previous
#include <cuda_runtime.h>
#include <cuda_bf16.h>
#include <cstdint>

constexpr int STATE = 2048;
constexpr int SEQL  = 4096;
constexpr int HID   = 1024;
constexpr int KP    = 3 * HID;     // [hi|hi|lo] x [hi|lo|hi] split-K layout

constexpr int BK  = 64;            // 64 bf16 = 128B row = one SW128 atom
constexpr int NIT = KP / BK;       // 48
constexpr int NSTG = 3;

__device__ __align__(128) __nv_bfloat16 g_idS  [(size_t)SEQL  * KP];  // pat1
__device__ __align__(128) __nv_bfloat16 g_WTS  [(size_t)HID   * KP];  // W^T, pat1
__device__ __align__(128) __nv_bfloat16 g_combS[(size_t)STATE * KP];  // pat0
__device__ __align__(128) __nv_bfloat16 g_PS   [(size_t)STATE * KP];  // P=comb@W, pat0

// ---------------------------------------------------------------------------
__device__ __forceinline__ uint32_t smem_u32(const void* p) {
    uint32_t a;
    asm("{ .reg .u64 t; cvta.to.shared.u64 t, %1; cvt.u32.u64 %0, t; }" : "=r"(a) : "l"(p));
    return a;
}
__device__ __forceinline__ uint32_t sw128(uint32_t off) { return off ^ ((off >> 3) & 0x70); }
__device__ __forceinline__ void cp_async16(uint32_t s, const void* g) {
    asm volatile("cp.async.cg.shared.global [%0], [%1], 16;" :: "r"(s), "l"(g) : "memory");
}
__device__ __forceinline__ void ldsm_x4(uint32_t* r, uint32_t addr) {
    asm volatile("ldmatrix.sync.aligned.m8n8.x4.shared.b16 {%0,%1,%2,%3}, [%4];"
                 : "=r"(r[0]), "=r"(r[1]), "=r"(r[2]), "=r"(r[3]) : "r"(addr));
}
__device__ __forceinline__ void mma_bf16(float* c, const uint32_t* a, const uint32_t* b) {
    asm volatile(
        "mma.sync.aligned.m16n8k16.row.col.f32.bf16.bf16.f32 "
        "{%0,%1,%2,%3}, {%4,%5,%6,%7}, {%8,%9}, {%0,%1,%2,%3};"
        : "+f"(c[0]), "+f"(c[1]), "+f"(c[2]), "+f"(c[3])
        : "r"(a[0]), "r"(a[1]), "r"(a[2]), "r"(a[3]), "r"(b[0]), "r"(b[1]));
}
__device__ __forceinline__ uint32_t pack_bf16(float x, float y) {
    __nv_bfloat162 t = __floats2bfloat162_rn(x, y);
    return *reinterpret_cast<uint32_t*>(&t);
}

// ------------------ split helpers: fp32 -> bf16 (hi,lo) triplets ------------
__device__ __forceinline__ void split_store(float x0, float x1, float x2, float x3,
                                            __nv_bfloat16* dst, size_t base, int pat) {
    alignas(8) __nv_bfloat16 h[4], l[4];
    float x[4] = {x0, x1, x2, x3};
    #pragma unroll
    for (int c = 0; c < 4; c++) {
        h[c] = __float2bfloat16_rn(x[c]);
        l[c] = __float2bfloat16_rn(x[c] - __bfloat162float(h[c]));
    }
    const uint2 hw = *reinterpret_cast<uint2*>(h);
    const uint2 lw = *reinterpret_cast<uint2*>(l);
    *reinterpret_cast<uint2*>(dst + base) = hw;
    if (pat == 0) {  // A-operand: [hi|hi|lo]
        *reinterpret_cast<uint2*>(dst + base + HID)     = hw;
        *reinterpret_cast<uint2*>(dst + base + 2 * HID) = lw;
    } else {         // B-operand: [hi|lo|hi]
        *reinterpret_cast<uint2*>(dst + base + HID)     = lw;
        *reinterpret_cast<uint2*>(dst + base + 2 * HID) = hw;
    }
}

template <int PAT>
__global__ __launch_bounds__(256)
void split_kernel(const float* __restrict__ src, __nv_bfloat16* __restrict__ dst) {
    const int i = blockIdx.x * 256 + threadIdx.x;
    const float4 v = reinterpret_cast<const float4*>(src)[i];
    const int row = i >> 8;
    const int col = (i & 255) << 2;
    split_store(v.x, v.y, v.z, v.w, dst, (size_t)row * KP + col, PAT);
}

__global__ __launch_bounds__(256)
void combine_split_kernel(const float* __restrict__ u, const float* __restrict__ s,
                          const float* __restrict__ w1p, const float* __restrict__ w2p,
                          __nv_bfloat16* __restrict__ dst) {
    const float w1 = *w1p, w2 = *w2p;
    const int i = blockIdx.x * 256 + threadIdx.x;
    const float4 uv = reinterpret_cast<const float4*>(u)[i];
    const float4 sv = reinterpret_cast<const float4*>(s)[i];
    const int row = i >> 8;
    const int col = (i & 255) << 2;
    split_store(fmaf(w1, uv.x, w2 * sv.x), fmaf(w1, uv.y, w2 * sv.y),
                fmaf(w1, uv.z, w2 * sv.z), fmaf(w1, uv.w, w2 * sv.w),
                dst, (size_t)row * KP + col, 0);
}

// Transpose + split: dst[h, triplet over n] = W[n, h], pat1. 32x32 tiles.
__global__ __launch_bounds__(256)
void transpose_split_kernel(const float* __restrict__ W, __nv_bfloat16* __restrict__ dst) {
    __shared__ float ts[32][33];
    const int tx = threadIdx.x & 31;
    const int ty = threadIdx.x >> 5;
    const int n0 = blockIdx.y * 32;
    const int h0 = blockIdx.x * 32;
    #pragma unroll
    for (int j = 0; j < 4; j++)
        ts[ty + j * 8][tx] = W[(size_t)(n0 + ty + j * 8) * HID + h0 + tx];
    __syncthreads();
    const int r  = threadIdx.x >> 3;
    const int c4 = (threadIdx.x & 7) * 4;
    split_store(ts[c4 + 0][r], ts[c4 + 1][r], ts[c4 + 2][r], ts[c4 + 3][r],
                dst, (size_t)(h0 + r) * KP + n0 + c4, 1);
}

// ------------------ HMMA NT GEMM -------------------------------------------
// Warp tile fixed at 64x32 (proven): WROWS=TBM/WARPS_M must be 64, cols TBN/WARPS_N=32.
// MODE 0: fp32 out (stride Nout). MODE 1: bf16 pat0 split of D -> PS.
template <int MODE, int TBM, int TBN, int WARPS_M, int WARPS_N, int OCC>
__global__ __launch_bounds__(WARPS_M * WARPS_N * 32, OCC)
void gemm_mma_kernel(const __nv_bfloat16* __restrict__ A,
                     const __nv_bfloat16* __restrict__ B,
                     void* __restrict__ outp, int Nout) {
    constexpr int THREADS = WARPS_M * WARPS_N * 32;
    constexpr int WROWS   = TBM / WARPS_M;
    constexpr int MT      = WROWS / 16;           // 4
    constexpr int A_STG   = TBM * 128;
    constexpr int B_STG   = TBN * 128;
    constexpr int STG     = A_STG + B_STG;
    static_assert(WROWS == 64, "warp tile M must be 64");
    static_assert(TBN / WARPS_N == 32, "warp tile N must be 32");

    extern __shared__ __align__(1024) char smem_raw[];
    const uint32_t sb = smem_u32(smem_raw);
    const int tid  = threadIdx.x;
    const int lane = tid & 31;
    const int wid  = tid >> 5;
    const int wm   = wid % WARPS_M;
    const int wn   = wid / WARPS_M;
    const int m0   = blockIdx.y * TBM;
    const int n0   = blockIdx.x * TBN;

    auto load_stage = [&](int it) {
        const int st = (it % NSTG);
        const size_t k0 = (size_t)it * BK;
        const uint32_t sa  = sb + st * STG;
        const uint32_t sbb = sa + A_STG;
        #pragma unroll
        for (int j = 0; j < TBM * 8 / THREADS; j++) {   // A: TBM rows x 128B
            const int c = tid + j * THREADS;
            const int r = c >> 3, p = c & 7;
            cp_async16(sa + sw128((uint32_t)(r * 128 + p * 16)),
                       A + (size_t)(m0 + r) * KP + k0 + p * 8);
        }
        #pragma unroll
        for (int j = 0; j < TBN * 8 / THREADS; j++) {   // B: TBN rows x 128B
            const int c = tid + j * THREADS;
            const int r = c >> 3, p = c & 7;
            cp_async16(sbb + sw128((uint32_t)(r * 128 + p * 16)),
                       B + (size_t)(n0 + r) * KP + k0 + p * 8);
        }
        asm volatile("cp.async.commit_group;" ::: "memory");
    };

    float acc[MT][4][4];
    #pragma unroll
    for (int mt = 0; mt < MT; mt++)
        #pragma unroll
        for (int nt = 0; nt < 4; nt++)
            #pragma unroll
            for (int q = 0; q < 4; q++) acc[mt][nt][q] = 0.f;

    const uint32_t rA0 = (uint32_t)((wm * WROWS + (lane & 15)) * 128 + ((lane >> 4) << 4));
    const uint32_t rB0 = (uint32_t)((wn * 32 + ((lane >> 4) << 3) + (lane & 7)) * 128
                                    + ((lane & 8) << 1));

    load_stage(0); load_stage(1);

    for (int it = 0; it < NIT; ++it) {
        if (it + 2 < NIT) { asm volatile("cp.async.wait_group 1;" ::: "memory"); }
        else              { asm volatile("cp.async.wait_group 0;" ::: "memory"); }
        __syncthreads();
        if (it + 2 < NIT) load_stage(it + 2);

        const uint32_t sa  = sb + (it % NSTG) * STG;
        const uint32_t sbb = sa + A_STG;
        #pragma unroll
        for (int kk = 0; kk < 4; kk++) {            // 4 x k16 per BK=64
            uint32_t a[MT][4], b[2][4];
            #pragma unroll
            for (int mt2 = 0; mt2 < MT; mt2++)
                ldsm_x4(a[mt2], sa + sw128(rA0 + mt2 * 2048 + kk * 32));
            #pragma unroll
            for (int nt2 = 0; nt2 < 2; nt2++)
                ldsm_x4(b[nt2], sbb + sw128(rB0 + nt2 * 2048 + kk * 32));
            #pragma unroll
            for (int nt = 0; nt < 4; nt++) {
                const uint32_t* bp = &b[nt >> 1][(nt & 1) * 2];
                #pragma unroll
                for (int mt = 0; mt < MT; mt++)
                    mma_bf16(acc[mt][nt], a[mt], bp);
            }
        }
    }

    // ------------- epilogue (register-direct) -------------
    #pragma unroll
    for (int mt = 0; mt < MT; mt++) {
        const int r0 = m0 + wm * WROWS + mt * 16 + (lane >> 2);
        #pragma unroll
        for (int nt = 0; nt < 4; nt++) {
            const int col = n0 + wn * 32 + nt * 8 + (lane & 3) * 2;
            const float x0 = acc[mt][nt][0], x1 = acc[mt][nt][1];
            const float x2 = acc[mt][nt][2], x3 = acc[mt][nt][3];
            if (MODE == 0) {
                float* of = (float*)outp;
                *reinterpret_cast<float2*>(&of[(size_t)r0 * Nout + col])       = make_float2(x0, x1);
                *reinterpret_cast<float2*>(&of[(size_t)(r0 + 8) * Nout + col]) = make_float2(x2, x3);
            } else {
                __nv_bfloat16* ob = (__nv_bfloat16*)outp;
                {   // row r0, pat0: [hi|hi|lo]
                    const __nv_bfloat16 h0 = __float2bfloat16_rn(x0);
                    const __nv_bfloat16 h1 = __float2bfloat16_rn(x1);
                    const uint32_t hw = pack_bf16(__bfloat162float(h0), __bfloat162float(h1));
                    const uint32_t lw = pack_bf16(x0 - __bfloat162float(h0), x1 - __bfloat162float(h1));
                    const size_t base = (size_t)r0 * KP + col;
                    *reinterpret_cast<uint32_t*>(ob + base)           = hw;
                    *reinterpret_cast<uint32_t*>(ob + base + HID)     = hw;
                    *reinterpret_cast<uint32_t*>(ob + base + 2 * HID) = lw;
                }
                {   // row r0+8
                    const __nv_bfloat16 h0 = __float2bfloat16_rn(x2);
                    const __nv_bfloat16 h1 = __float2bfloat16_rn(x3);
                    const uint32_t hw = pack_bf16(__bfloat162float(h0), __bfloat162float(h1));
                    const uint32_t lw = pack_bf16(x2 - __bfloat162float(h0), x3 - __bfloat162float(h1));
                    const size_t base = (size_t)(r0 + 8) * KP + col;
                    *reinterpret_cast<uint32_t*>(ob + base)           = hw;
                    *reinterpret_cast<uint32_t*>(ob + base + HID)     = hw;
                    *reinterpret_cast<uint32_t*>(ob + base + 2 * HID) = lw;
                }
            }
        }
    }
}

// ------------------ softmax ------------------------------------------------
__global__ __launch_bounds__(256)
void softmax_kernel(float* __restrict__ data) {
    constexpr int N = SEQL;
    __shared__ float sh[N];
    __shared__ float red[256];
    const int tid = threadIdx.x;
    float* row = data + (size_t)blockIdx.x * N;

    float mx = -3.402823466e38f;
    #pragma unroll
    for (int it = 0; it < 4; ++it) {
        const int i = tid + it * 256;
        const float4 v = reinterpret_cast<const float4*>(row)[i];
        reinterpret_cast<float4*>(sh)[i] = v;
        mx = fmaxf(mx, fmaxf(fmaxf(v.x, v.y), fmaxf(v.z, v.w)));
    }
    red[tid] = mx;
    __syncthreads();
    for (int s = 128; s > 0; s >>= 1) {
        if (tid < s) red[tid] = fmaxf(red[tid], red[tid + s]);
        __syncthreads();
    }
    mx = red[0];
    __syncthreads();

    float sum = 0.f;
    #pragma unroll
    for (int it = 0; it < 4; ++it) {
        const int i = tid + it * 256;
        float4 v = reinterpret_cast<float4*>(sh)[i];
        v.x = expf(v.x - mx); v.y = expf(v.y - mx);
        v.z = expf(v.z - mx); v.w = expf(v.w - mx);
        reinterpret_cast<float4*>(sh)[i] = v;
        sum += v.x + v.y + v.z + v.w;
    }
    red[tid] = sum;
    __syncthreads();
    for (int s = 128; s > 0; s >>= 1) {
        if (tid < s) red[tid] += red[tid + s];
        __syncthreads();
    }
    const float inv = 1.f / red[0];

    #pragma unroll
    for (int it = 0; it < 4; ++it) {
        const int i = tid + it * 256;
        float4 v = reinterpret_cast<float4*>(sh)[i];
        v.x *= inv; v.y *= inv; v.z *= inv; v.w *= inv;
        reinterpret_cast<float4*>(row)[i] = v;
    }
}

// ------------------ kernel_launch ------------------------------------------
extern "C" void kernel_launch(void* const* d_in, const int* in_sizes, int n_in,
                              void* d_out, int out_size) {
    const float* user = (const float*)d_in[0];
    const float* id   = (const float*)d_in[1];
    const float* soc  = (const float*)d_in[2];
    const float* W    = (const float*)d_in[3];
    // d_in[4] = bias: unused — softmax is invariant to the per-row constant comb.b
    const float* w1   = (const float*)d_in[5];
    const float* w2   = (const float*)d_in[6];
    float* out = (float*)d_out;

    void *pIdS, *pWTS, *pCombS, *pPS;
    cudaGetSymbolAddress(&pIdS,   g_idS);
    cudaGetSymbolAddress(&pWTS,   g_WTS);
    cudaGetSymbolAddress(&pCombS, g_combS);
    cudaGetSymbolAddress(&pPS,    g_PS);
    __nv_bfloat16* idS   = (__nv_bfloat16*)pIdS;
    __nv_bfloat16* WTS   = (__nv_bfloat16*)pWTS;
    __nv_bfloat16* combS = (__nv_bfloat16*)pCombS;
    __nv_bfloat16* PS    = (__nv_bfloat16*)pPS;

    // gemm<0>: R8 champion config — tile 128x128, warps 2Mx4N, 256 thr, 2 CTAs/SM
    constexpr int SMEM0 = NSTG * (128 * 128 + 128 * 128);   // 96KB
    // gemm<1>: tile 64x128, warps 1Mx4N (warp tile 64x32), 128 thr, 3 CTAs/SM
    constexpr int SMEM1 = NSTG * (64 * 128 + 128 * 128);    // 72KB
    cudaFuncSetAttribute((const void*)gemm_mma_kernel<0, 128, 128, 2, 4, 2>,
                         cudaFuncAttributeMaxDynamicSharedMemorySize, SMEM0);
    cudaFuncSetAttribute((const void*)gemm_mma_kernel<1, 64, 128, 1, 4, 3>,
                         cudaFuncAttributeMaxDynamicSharedMemorySize, SMEM1);

    // 1) operand splits
    combine_split_kernel<<<(STATE * HID / 4) / 256, 256>>>(user, soc, w1, w2, combS);  // pat0
    split_kernel<1><<<(SEQL * HID / 4) / 256, 256>>>(id, idS);                          // pat1
    transpose_split_kernel<<<dim3(HID / 32, HID / 32), 256>>>(W, WTS);                  // pat1

    // 2) P = comb @ W  -> pat0 split into PS      (grid 8 x 32 = 256 CTAs, 3/SM)
    gemm_mma_kernel<1, 64, 128, 1, 4, 3>
        <<<dim3(HID / 128, STATE / 64), 128, SMEM1>>>(combS, WTS, PS, 0);

    // 3) energies = P @ id^T -> d_out (fp32)      (grid 32 x 16 = 512 CTAs, 2/SM)
    gemm_mma_kernel<0, 128, 128, 2, 4, 2>
        <<<dim3(SEQL / 128, STATE / 128), 256, SMEM0>>>(PS, idS, out, SEQL);

    // 4) softmax rows in place
    softmax_kernel<<<STATE, 256>>>(out);
}

// round 13
// speedup vs baseline: 1.0364x; 1.0091x over previous
#include <cuda_runtime.h>
#include <cuda_bf16.h>
#include <cstdint>

constexpr int STATE = 2048;
constexpr int SEQL  = 4096;
constexpr int HID   = 1024;
constexpr int KP    = 3 * HID;     // [hi|hi|lo] x [hi|lo|hi] split-K layout

constexpr int BK  = 64;            // 64 bf16 = 128B row = one SW128 atom
constexpr int NSTG = 3;

__device__ __align__(128) __nv_bfloat16 g_idS  [(size_t)SEQL  * KP];  // pat1
__device__ __align__(128) __nv_bfloat16 g_WTS  [(size_t)HID   * KP];  // W^T, pat1
__device__ __align__(128) __nv_bfloat16 g_combS[(size_t)STATE * KP];  // pat0
__device__ __align__(128) __nv_bfloat16 g_PS   [(size_t)STATE * KP];  // P=comb@W, pat0
__device__ __align__(128) float          g_P32 [2 * (size_t)STATE * HID];  // split-K partials

// ---------------------------------------------------------------------------
__device__ __forceinline__ uint32_t smem_u32(const void* p) {
    uint32_t a;
    asm("{ .reg .u64 t; cvta.to.shared.u64 t, %1; cvt.u32.u64 %0, t; }" : "=r"(a) : "l"(p));
    return a;
}
__device__ __forceinline__ uint32_t sw128(uint32_t off) { return off ^ ((off >> 3) & 0x70); }
__device__ __forceinline__ void cp_async16(uint32_t s, const void* g) {
    asm volatile("cp.async.cg.shared.global [%0], [%1], 16;" :: "r"(s), "l"(g) : "memory");
}
__device__ __forceinline__ void ldsm_x4(uint32_t* r, uint32_t addr) {
    asm volatile("ldmatrix.sync.aligned.m8n8.x4.shared.b16 {%0,%1,%2,%3}, [%4];"
                 : "=r"(r[0]), "=r"(r[1]), "=r"(r[2]), "=r"(r[3]) : "r"(addr));
}
__device__ __forceinline__ void mma_bf16(float* c, const uint32_t* a, const uint32_t* b) {
    asm volatile(
        "mma.sync.aligned.m16n8k16.row.col.f32.bf16.bf16.f32 "
        "{%0,%1,%2,%3}, {%4,%5,%6,%7}, {%8,%9}, {%0,%1,%2,%3};"
        : "+f"(c[0]), "+f"(c[1]), "+f"(c[2]), "+f"(c[3])
        : "r"(a[0]), "r"(a[1]), "r"(a[2]), "r"(a[3]), "r"(b[0]), "r"(b[1]));
}
__device__ __forceinline__ uint32_t pack_bf16(float x, float y) {
    __nv_bfloat162 t = __floats2bfloat162_rn(x, y);
    return *reinterpret_cast<uint32_t*>(&t);
}

// ------------------ split helpers: fp32 -> bf16 (hi,lo) triplets ------------
__device__ __forceinline__ void split_store(float x0, float x1, float x2, float x3,
                                            __nv_bfloat16* dst, size_t base, int pat) {
    alignas(8) __nv_bfloat16 h[4], l[4];
    float x[4] = {x0, x1, x2, x3};
    #pragma unroll
    for (int c = 0; c < 4; c++) {
        h[c] = __float2bfloat16_rn(x[c]);
        l[c] = __float2bfloat16_rn(x[c] - __bfloat162float(h[c]));
    }
    const uint2 hw = *reinterpret_cast<uint2*>(h);
    const uint2 lw = *reinterpret_cast<uint2*>(l);
    *reinterpret_cast<uint2*>(dst + base) = hw;
    if (pat == 0) {  // A-operand: [hi|hi|lo]
        *reinterpret_cast<uint2*>(dst + base + HID)     = hw;
        *reinterpret_cast<uint2*>(dst + base + 2 * HID) = lw;
    } else {         // B-operand: [hi|lo|hi]
        *reinterpret_cast<uint2*>(dst + base + HID)     = lw;
        *reinterpret_cast<uint2*>(dst + base + 2 * HID) = hw;
    }
}

template <int PAT>
__global__ __launch_bounds__(256)
void split_kernel(const float* __restrict__ src, __nv_bfloat16* __restrict__ dst) {
    const int i = blockIdx.x * 256 + threadIdx.x;
    const float4 v = reinterpret_cast<const float4*>(src)[i];
    const int row = i >> 8;
    const int col = (i & 255) << 2;
    split_store(v.x, v.y, v.z, v.w, dst, (size_t)row * KP + col, PAT);
}

__global__ __launch_bounds__(256)
void combine_split_kernel(const float* __restrict__ u, const float* __restrict__ s,
                          const float* __restrict__ w1p, const float* __restrict__ w2p,
                          __nv_bfloat16* __restrict__ dst) {
    const float w1 = *w1p, w2 = *w2p;
    const int i = blockIdx.x * 256 + threadIdx.x;
    const float4 uv = reinterpret_cast<const float4*>(u)[i];
    const float4 sv = reinterpret_cast<const float4*>(s)[i];
    const int row = i >> 8;
    const int col = (i & 255) << 2;
    split_store(fmaf(w1, uv.x, w2 * sv.x), fmaf(w1, uv.y, w2 * sv.y),
                fmaf(w1, uv.z, w2 * sv.z), fmaf(w1, uv.w, w2 * sv.w),
                dst, (size_t)row * KP + col, 0);
}

// Transpose + split: dst[h, triplet over n] = W[n, h], pat1. 32x32 tiles.
__global__ __launch_bounds__(256)
void transpose_split_kernel(const float* __restrict__ W, __nv_bfloat16* __restrict__ dst) {
    __shared__ float ts[32][33];
    const int tx = threadIdx.x & 31;
    const int ty = threadIdx.x >> 5;
    const int n0 = blockIdx.y * 32;
    const int h0 = blockIdx.x * 32;
    #pragma unroll
    for (int j = 0; j < 4; j++)
        ts[ty + j * 8][tx] = W[(size_t)(n0 + ty + j * 8) * HID + h0 + tx];
    __syncthreads();
    const int r  = threadIdx.x >> 3;
    const int c4 = (threadIdx.x & 7) * 4;
    split_store(ts[c4 + 0][r], ts[c4 + 1][r], ts[c4 + 2][r], ts[c4 + 3][r],
                dst, (size_t)(h0 + r) * KP + n0 + c4, 1);
}

// Sum two split-K partials and re-split pat0 into PS.
__global__ __launch_bounds__(256)
void add_split_kernel(const float* __restrict__ p0, const float* __restrict__ p1,
                      __nv_bfloat16* __restrict__ dst) {
    const int i = blockIdx.x * 256 + threadIdx.x;   // float4 index
    const float4 a = reinterpret_cast<const float4*>(p0)[i];
    const float4 b = reinterpret_cast<const float4*>(p1)[i];
    const int row = i >> 8;
    const int col = (i & 255) << 2;
    split_store(a.x + b.x, a.y + b.y, a.z + b.z, a.w + b.w,
                dst, (size_t)row * KP + col, 0);
}

// ------------------ HMMA NT GEMM (fp32 out) --------------------------------
// Champion shape: tile 128x128, 8 warps as 2(M) x 4(N), warp tile 64x32, 2 CTAs/SM.
// NITT k-iterations starting at kOff = blockIdx.z * kSlice elements.
// Output: fp32, row stride Nout, plus blockIdx.z * zStride element offset.
template <int NITT>
__global__ __launch_bounds__(256, 2)
void gemm_mma_kernel(const __nv_bfloat16* __restrict__ A,
                     const __nv_bfloat16* __restrict__ B,
                     float* __restrict__ outp, int Nout,
                     int kSlice, size_t zStride) {
    constexpr int TBM = 128, TBN = 128;
    constexpr int A_STG = TBM * 128;
    constexpr int B_STG = TBN * 128;
    constexpr int STG   = A_STG + B_STG;      // 32KB

    extern __shared__ __align__(1024) char smem_raw[];
    const uint32_t sb = smem_u32(smem_raw);
    const int tid  = threadIdx.x;
    const int lane = tid & 31;
    const int wid  = tid >> 5;
    const int wm   = wid & 1;        // 2 warps along M (64 rows each)
    const int wn   = wid >> 1;       // 4 warps along N (32 cols each)
    const int m0   = blockIdx.y * TBM;
    const int n0   = blockIdx.x * TBN;
    const size_t kOff = (size_t)blockIdx.z * kSlice;

    auto load_stage = [&](int it) {
        const int st = (it % NSTG);
        const size_t k0 = kOff + (size_t)it * BK;
        const uint32_t sa  = sb + st * STG;
        const uint32_t sbb = sa + A_STG;
        #pragma unroll
        for (int j = 0; j < 4; j++) {              // A: 128 rows x 128B
            const int c = tid + j * 256;
            const int r = c >> 3, p = c & 7;
            cp_async16(sa + sw128((uint32_t)(r * 128 + p * 16)),
                       A + (size_t)(m0 + r) * KP + k0 + p * 8);
        }
        #pragma unroll
        for (int j = 0; j < 4; j++) {              // B: 128 rows x 128B
            const int c = tid + j * 256;
            const int r = c >> 3, p = c & 7;
            cp_async16(sbb + sw128((uint32_t)(r * 128 + p * 16)),
                       B + (size_t)(n0 + r) * KP + k0 + p * 8);
        }
        asm volatile("cp.async.commit_group;" ::: "memory");
    };

    float acc[4][4][4];
    #pragma unroll
    for (int mt = 0; mt < 4; mt++)
        #pragma unroll
        for (int nt = 0; nt < 4; nt++)
            #pragma unroll
            for (int q = 0; q < 4; q++) acc[mt][nt][q] = 0.f;

    const uint32_t rA0 = (uint32_t)((wm * 64 + (lane & 15)) * 128 + ((lane >> 4) << 4));
    const uint32_t rB0 = (uint32_t)((wn * 32 + ((lane >> 4) << 3) + (lane & 7)) * 128
                                    + ((lane & 8) << 1));

    load_stage(0); load_stage(1);

    for (int it = 0; it < NITT; ++it) {
        if (it + 2 < NITT) { asm volatile("cp.async.wait_group 1;" ::: "memory"); }
        else               { asm volatile("cp.async.wait_group 0;" ::: "memory"); }
        __syncthreads();
        if (it + 2 < NITT) load_stage(it + 2);

        const uint32_t sa  = sb + (it % NSTG) * STG;
        const uint32_t sbb = sa + A_STG;
        #pragma unroll
        for (int kk = 0; kk < 4; kk++) {            // 4 x k16 per BK=64
            uint32_t a[4][4], b[2][4];
            #pragma unroll
            for (int mt2 = 0; mt2 < 4; mt2++)
                ldsm_x4(a[mt2], sa + sw128(rA0 + mt2 * 2048 + kk * 32));
            #pragma unroll
            for (int nt2 = 0; nt2 < 2; nt2++)
                ldsm_x4(b[nt2], sbb + sw128(rB0 + nt2 * 2048 + kk * 32));
            #pragma unroll
            for (int nt = 0; nt < 4; nt++) {
                const uint32_t* bp = &b[nt >> 1][(nt & 1) * 2];
                #pragma unroll
                for (int mt = 0; mt < 4; mt++)
                    mma_bf16(acc[mt][nt], a[mt], bp);
            }
        }
    }

    // ------------- epilogue: fp32 register-direct -------------
    float* of = outp + (size_t)blockIdx.z * zStride;
    #pragma unroll
    for (int mt = 0; mt < 4; mt++) {
        const int r0 = m0 + wm * 64 + mt * 16 + (lane >> 2);
        #pragma unroll
        for (int nt = 0; nt < 4; nt++) {
            const int col = n0 + wn * 32 + nt * 8 + (lane & 3) * 2;
            *reinterpret_cast<float2*>(&of[(size_t)r0 * Nout + col]) =
                make_float2(acc[mt][nt][0], acc[mt][nt][1]);
            *reinterpret_cast<float2*>(&of[(size_t)(r0 + 8) * Nout + col]) =
                make_float2(acc[mt][nt][2], acc[mt][nt][3]);
        }
    }
}

// ------------------ softmax ------------------------------------------------
__global__ __launch_bounds__(256)
void softmax_kernel(float* __restrict__ data) {
    constexpr int N = SEQL;
    __shared__ float sh[N];
    __shared__ float red[256];
    const int tid = threadIdx.x;
    float* row = data + (size_t)blockIdx.x * N;

    float mx = -3.402823466e38f;
    #pragma unroll
    for (int it = 0; it < 4; ++it) {
        const int i = tid + it * 256;
        const float4 v = reinterpret_cast<const float4*>(row)[i];
        reinterpret_cast<float4*>(sh)[i] = v;
        mx = fmaxf(mx, fmaxf(fmaxf(v.x, v.y), fmaxf(v.z, v.w)));
    }
    red[tid] = mx;
    __syncthreads();
    for (int s = 128; s > 0; s >>= 1) {
        if (tid < s) red[tid] = fmaxf(red[tid], red[tid + s]);
        __syncthreads();
    }
    mx = red[0];
    __syncthreads();

    float sum = 0.f;
    #pragma unroll
    for (int it = 0; it < 4; ++it) {
        const int i = tid + it * 256;
        float4 v = reinterpret_cast<float4*>(sh)[i];
        v.x = __expf(v.x - mx); v.y = __expf(v.y - mx);
        v.z = __expf(v.z - mx); v.w = __expf(v.w - mx);
        reinterpret_cast<float4*>(sh)[i] = v;
        sum += v.x + v.y + v.z + v.w;
    }
    red[tid] = sum;
    __syncthreads();
    for (int s = 128; s > 0; s >>= 1) {
        if (tid < s) red[tid] += red[tid + s];
        __syncthreads();
    }
    const float inv = 1.f / red[0];

    #pragma unroll
    for (int it = 0; it < 4; ++it) {
        const int i = tid + it * 256;
        float4 v = reinterpret_cast<float4*>(sh)[i];
        v.x *= inv; v.y *= inv; v.z *= inv; v.w *= inv;
        reinterpret_cast<float4*>(row)[i] = v;
    }
}

// ------------------ kernel_launch ------------------------------------------
extern "C" void kernel_launch(void* const* d_in, const int* in_sizes, int n_in,
                              void* d_out, int out_size) {
    const float* user = (const float*)d_in[0];
    const float* id   = (const float*)d_in[1];
    const float* soc  = (const float*)d_in[2];
    const float* W    = (const float*)d_in[3];
    // d_in[4] = bias: unused — softmax is invariant to the per-row constant comb.b
    const float* w1   = (const float*)d_in[5];
    const float* w2   = (const float*)d_in[6];
    float* out = (float*)d_out;

    void *pIdS, *pWTS, *pCombS, *pPS, *pP32;
    cudaGetSymbolAddress(&pIdS,   g_idS);
    cudaGetSymbolAddress(&pWTS,   g_WTS);
    cudaGetSymbolAddress(&pCombS, g_combS);
    cudaGetSymbolAddress(&pPS,    g_PS);
    cudaGetSymbolAddress(&pP32,   g_P32);
    __nv_bfloat16* idS   = (__nv_bfloat16*)pIdS;
    __nv_bfloat16* WTS   = (__nv_bfloat16*)pWTS;
    __nv_bfloat16* combS = (__nv_bfloat16*)pCombS;
    __nv_bfloat16* PS    = (__nv_bfloat16*)pPS;
    float*         P32   = (float*)pP32;

    constexpr int SMEM_SZ = NSTG * (128 * 128 + 128 * 128);   // 96KB
    cudaFuncSetAttribute((const void*)gemm_mma_kernel<48>,
                         cudaFuncAttributeMaxDynamicSharedMemorySize, SMEM_SZ);
    cudaFuncSetAttribute((const void*)gemm_mma_kernel<24>,
                         cudaFuncAttributeMaxDynamicSharedMemorySize, SMEM_SZ);

    // 1) operand splits
    combine_split_kernel<<<(STATE * HID / 4) / 256, 256>>>(user, soc, w1, w2, combS);  // pat0
    split_kernel<1><<<(SEQL * HID / 4) / 256, 256>>>(id, idS);                          // pat1
    transpose_split_kernel<<<dim3(HID / 32, HID / 32), 256>>>(W, WTS);                  // pat1

    // 2) P partials = comb @ W (split-K=2) -> fp32   (grid 8 x 16 x 2 = 256 CTAs, 2/SM)
    gemm_mma_kernel<24><<<dim3(HID / 128, STATE / 128, 2), 256, SMEM_SZ>>>(
        combS, WTS, P32, HID, /*kSlice=*/KP / 2, /*zStride=*/(size_t)STATE * HID);

    // 2b) PS = pat0split(P32[0] + P32[1])
    add_split_kernel<<<(STATE * HID / 4) / 256, 256>>>(P32, P32 + (size_t)STATE * HID, PS);

    // 3) energies = P @ id^T -> d_out (fp32)          (grid 32 x 16 = 512 CTAs, 2/SM)
    gemm_mma_kernel<48><<<dim3(SEQL / 128, STATE / 128, 1), 256, SMEM_SZ>>>(
        PS, idS, out, SEQL, 0, 0);

    // 4) softmax rows in place
    softmax_kernel<<<STATE, 256>>>(out);
}